// round 6
// baseline (speedup 1.0000x reference)
#include <cuda_runtime.h>
#include <math.h>
#include <cstdint>

#define B_  64
#define T_  218
#define D_  512
#define R_  (B_*T_)      // 13952 = 109*128
#define H_  4
#define DK_ 128
#define QKVW (3*D_)      // 1536

// ---------------- scratch (device globals; no allocations allowed) ----------
__device__ float g_h[R_*D_];                  // PERMUTED k-layout
__device__ float g_qkv[R_*QKVW];              // natural
__device__ float g_vm[R_*D_];                 // PERMUTED
__device__ float g_fsmn[R_*D_];               // natural
__device__ float g_ctx[R_*D_];                // PERMUTED
__device__ float g_x1[R_*D_];                 // natural
__device__ float g_mid[R_*2048];              // PERMUTED
__device__ float g_qkv_wt[QKVW*D_];           // [N,K] K-permuted, tf32
__device__ float g_out_wt[D_*D_];             // K-permuted
__device__ float g_w1t[2048*D_];              // K-permuted
__device__ float g_w2t[D_*2048];              // K-permuted
__device__ float g_kwt[11*D_*D_];             // [tap][dout][din-permuted]

// ---------------- helpers ----------------------------------------------------
__device__ __forceinline__ float rna_tf32(float x) {
    float r; asm("cvt.rna.tf32.f32 %0,%1;" : "=f"(r) : "f"(x)); return r;
}
// permute within 32-blocks: logical k -> physical (k%4)*8 + k/4
__device__ __forceinline__ int pcol(int c) {
    return (c & ~31) | ((c & 3) << 3) | ((c & 31) >> 2);
}
__device__ __forceinline__ uint32_t smem_u32(const void* p) {
    uint32_t a;
    asm("{ .reg .u64 t; cvta.to.shared.u64 t, %1; cvt.u32.u64 %0, t; }" : "=r"(a) : "l"(p));
    return a;
}
__device__ __forceinline__ void cp16(uint32_t dst, const void* src, bool pred) {
    int sz = pred ? 16 : 0;
    asm volatile("cp.async.ca.shared.global [%0], [%1], 16, %2;"
                 :: "r"(dst), "l"(src), "r"(sz) : "memory");
}
#define CP_COMMIT() asm volatile("cp.async.commit_group;" ::: "memory")
#define CP_WAIT1()  asm volatile("cp.async.wait_group 1;" ::: "memory")
#define CP_WAIT0()  asm volatile("cp.async.wait_group 0;" ::: "memory")

#define MMA4(d, a0, a1, a2, a3, b0, b1) \
    asm volatile("mma.sync.aligned.m16n8k8.row.col.f32.tf32.tf32.f32 " \
                 "{%0,%1,%2,%3},{%4,%5,%6,%7},{%8,%9},{%0,%1,%2,%3};" \
                 : "+f"((d)[0]), "+f"((d)[1]), "+f"((d)[2]), "+f"((d)[3]) \
                 : "r"(a0), "r"(a1), "r"(a2), "r"(a3), "r"(b0), "r"(b1))

#define LDW 36                       // padded row width (floats); 144B rows -> 16B aligned
#define TILEF (128*LDW)
#define DSMEM_BYTES (4*TILEF*4)      // A0,B0,A1,B1 = 73728 B (2-stage)

// ---------------- weight transpose (+tf32 round, K-permute) -----------------
__global__ void transpose_rna(const float* __restrict__ src, float* __restrict__ dst,
                              int Kd, int Nd) {
    __shared__ float t[32][33];
    int k0 = blockIdx.y * 32, n0 = blockIdx.x * 32;
    int x = threadIdx.x, y = threadIdx.y;   // (32,8)
#pragma unroll
    for (int i = 0; i < 32; i += 8)
        t[y + i][x] = src[(size_t)(k0 + y + i) * Nd + n0 + x];
    __syncthreads();
    int px = ((x & 3) << 3) | (x >> 2);
#pragma unroll
    for (int i = 0; i < 32; i += 8)
        dst[(size_t)(n0 + y + i) * Kd + k0 + px] = rna_tf32(t[x][y + i]);
}

__global__ void kw_transpose(const float* __restrict__ fw) {
    int idx = blockIdx.x * 256 + threadIdx.x;
    if (idx >= 11 * D_ * D_) return;
    int tap = idx / (D_ * D_);
    int rem = idx % (D_ * D_);
    int dout = rem / D_;
    int din = rem % D_;
    g_kwt[(size_t)tap * D_ * D_ + (size_t)dout * D_ + pcol(din)] =
        rna_tf32(fw[((size_t)dout * D_ + din) * 11 + tap]);
}

// ---------------- layer norm (tf32-rounded, permuted output) ----------------
__global__ void ln_kernel(const float* __restrict__ x, const float* __restrict__ w,
                          const float* __restrict__ b, float* __restrict__ out) {
    int row = blockIdx.x;
    const float* xr = x + (size_t)row * D_;
    float* orow = out + (size_t)row * D_;
    float v[4];
    float s = 0.f, sq = 0.f;
#pragma unroll
    for (int i = 0; i < 4; i++) {
        v[i] = xr[threadIdx.x + i * 128];
        s += v[i]; sq += v[i] * v[i];
    }
    __shared__ float sm[8];
#pragma unroll
    for (int o = 16; o; o >>= 1) {
        s  += __shfl_xor_sync(~0u, s, o);
        sq += __shfl_xor_sync(~0u, sq, o);
    }
    int lane = threadIdx.x & 31, wid = threadIdx.x >> 5;
    if (lane == 0) { sm[wid] = s; sm[4 + wid] = sq; }
    __syncthreads();
    if (threadIdx.x == 0) {
        float S = sm[0] + sm[1] + sm[2] + sm[3];
        float SQ = sm[4] + sm[5] + sm[6] + sm[7];
        float mean = S * (1.f / D_);
        float var = SQ * (1.f / D_) - mean * mean;
        sm[0] = mean;
        sm[1] = rsqrtf(var + 1e-5f);
    }
    __syncthreads();
    float mean = sm[0], inv = sm[1];
#pragma unroll
    for (int i = 0; i < 4; i++) {
        int c = threadIdx.x + i * 128;
        orow[pcol(c)] = rna_tf32((v[i] - mean) * inv * w[c] + b[c]);
    }
}

// ---------------- tf32 mma.sync GEMM (2-stage, vectorized fragments) --------
// C[M,N] = A[M,K] @ Bt[N,K]^T + bias.  A,Bt stored K-permuted.
// epi: 0=bias; 1=bias+relu+round, C written K-PERMUTED (for mid);
//      2=bias+add1+add2; 3=bias+add1;
//      5=bias, plus cols>=1024 write vm=rna(v*mask) permuted (add1=masks, add2=vm)
__global__ void __launch_bounds__(256, 2)
tgemm(const float* __restrict__ A, const float* __restrict__ Bt,
      const float* __restrict__ bias, float* __restrict__ C,
      int N, int K, int epi,
      const float* __restrict__ add1, float* __restrict__ add2) {
    extern __shared__ float smf[];
    float* Abuf[2] = { smf,         smf + 2 * TILEF };
    float* Bbuf[2] = { smf + TILEF, smf + 3 * TILEF };
    int tid = threadIdx.x;
    int lane = tid & 31, wid = tid >> 5;
    int wm = (wid & 3) * 32;
    int wn = (wid >> 2) * 64;
    int g = lane >> 2, c = lane & 3;
    int rowBase = blockIdx.y * 128, colBase = blockIdx.x * 128;

    int srow[4], sseg[4];
#pragma unroll
    for (int u = 0; u < 4; u++) {
        int f = tid + 256 * u;
        srow[u] = f >> 3;
        sseg[u] = f & 7;
    }

    float acc[2][8][4];
#pragma unroll
    for (int i = 0; i < 2; i++)
#pragma unroll
        for (int j = 0; j < 8; j++)
#pragma unroll
            for (int q = 0; q < 4; q++) acc[i][j][q] = 0.f;

    int nk = K >> 5;
    const float* Arow = A + (size_t)rowBase * K;
    const float* Brow = Bt + (size_t)colBase * K;

#pragma unroll
    for (int u = 0; u < 4; u++) {
        cp16(smem_u32(Abuf[0] + srow[u] * LDW + sseg[u] * 4),
             Arow + (size_t)srow[u] * K + sseg[u] * 4, true);
        cp16(smem_u32(Bbuf[0] + srow[u] * LDW + sseg[u] * 4),
             Brow + (size_t)srow[u] * K + sseg[u] * 4, true);
    }
    CP_COMMIT();

    for (int kt = 0; kt < nk; kt++) {
        int buf = kt & 1;
        if (kt + 1 < nk) {
            int nb = buf ^ 1;
            const float* Ag = Arow + (size_t)(kt + 1) * 32;
            const float* Bg = Brow + (size_t)(kt + 1) * 32;
#pragma unroll
            for (int u = 0; u < 4; u++) {
                cp16(smem_u32(Abuf[nb] + srow[u] * LDW + sseg[u] * 4),
                     Ag + (size_t)srow[u] * K + sseg[u] * 4, true);
                cp16(smem_u32(Bbuf[nb] + srow[u] * LDW + sseg[u] * 4),
                     Bg + (size_t)srow[u] * K + sseg[u] * 4, true);
            }
            CP_COMMIT();
            CP_WAIT1();
        } else {
            CP_WAIT0();
        }
        __syncthreads();
        const float* As = Abuf[buf];
        const float* Bs = Bbuf[buf];

        // hoisted A fragments: 8 contiguous floats per row (all 4 k-steps)
        uint32_t af[2][2][8];
#pragma unroll
        for (int mt = 0; mt < 2; mt++)
#pragma unroll
            for (int rr = 0; rr < 2; rr++) {
                const float* ap = As + (wm + mt * 16 + g + rr * 8) * LDW + c * 8;
                float4 v0 = *(const float4*)ap;
                float4 v1 = *(const float4*)(ap + 4);
                af[mt][rr][0] = __float_as_uint(v0.x); af[mt][rr][1] = __float_as_uint(v0.y);
                af[mt][rr][2] = __float_as_uint(v0.z); af[mt][rr][3] = __float_as_uint(v0.w);
                af[mt][rr][4] = __float_as_uint(v1.x); af[mt][rr][5] = __float_as_uint(v1.y);
                af[mt][rr][6] = __float_as_uint(v1.z); af[mt][rr][7] = __float_as_uint(v1.w);
            }
#pragma unroll
        for (int nt = 0; nt < 8; nt++) {
            const float* bp = Bs + (wn + nt * 8 + g) * LDW + c * 8;
            float4 w0 = *(const float4*)bp;
            float4 w1 = *(const float4*)(bp + 4);
            uint32_t bf[8];
            bf[0] = __float_as_uint(w0.x); bf[1] = __float_as_uint(w0.y);
            bf[2] = __float_as_uint(w0.z); bf[3] = __float_as_uint(w0.w);
            bf[4] = __float_as_uint(w1.x); bf[5] = __float_as_uint(w1.y);
            bf[6] = __float_as_uint(w1.z); bf[7] = __float_as_uint(w1.w);
#pragma unroll
            for (int ks = 0; ks < 4; ks++) {
                MMA4(acc[0][nt], af[0][0][2*ks], af[0][1][2*ks],
                     af[0][0][2*ks+1], af[0][1][2*ks+1], bf[2*ks], bf[2*ks+1]);
                MMA4(acc[1][nt], af[1][0][2*ks], af[1][1][2*ks],
                     af[1][0][2*ks+1], af[1][1][2*ks+1], bf[2*ks], bf[2*ks+1]);
            }
        }
        __syncthreads();
    }

    // epilogue
#pragma unroll
    for (int mt = 0; mt < 2; mt++) {
#pragma unroll
        for (int nt = 0; nt < 8; nt++) {
            int cb = colBase + wn + nt * 8 + 2 * c;
            float bs0 = bias[cb], bs1 = bias[cb + 1];
#pragma unroll
            for (int half = 0; half < 2; half++) {
                int r = rowBase + wm + mt * 16 + g + half * 8;
                float v0 = acc[mt][nt][half * 2 + 0] + bs0;
                float v1 = acc[mt][nt][half * 2 + 1] + bs1;
                if (epi == 1) {
                    // relu + round, write K-permuted (mid feeds FFN2 as A)
                    C[(size_t)r * N + pcol(cb)]     = rna_tf32(fmaxf(v0, 0.f));
                    C[(size_t)r * N + pcol(cb + 1)] = rna_tf32(fmaxf(v1, 0.f));
                    continue;
                } else if (epi == 2) {
                    size_t id = (size_t)r * 512 + cb;
                    v0 += add1[id] + ((const float*)add2)[id];
                    v1 += add1[id + 1] + ((const float*)add2)[id + 1];
                } else if (epi == 3) {
                    size_t id = (size_t)r * 512 + cb;
                    v0 += add1[id];
                    v1 += add1[id + 1];
                }
                *(float2*)(C + (size_t)r * N + cb) = make_float2(v0, v1);
                if (epi == 5 && cb >= 1024) {
                    float m = add1[r];
                    add2[(size_t)r * 512 + pcol(cb - 1024)]     = rna_tf32(v0 * m);
                    add2[(size_t)r * 512 + pcol(cb - 1024 + 1)] = rna_tf32(v1 * m);
                }
            }
        }
    }
}

// ---------------- FSMN conv via mma.sync (2-stage, vectorized frags) --------
__global__ void __launch_bounds__(256, 2)
tconv(const float* __restrict__ vm, const float* __restrict__ qkv,
      const float* __restrict__ masks, float* __restrict__ out) {
    extern __shared__ float smf[];
    float* Abuf[2] = { smf,         smf + 2 * TILEF };
    float* Bbuf[2] = { smf + TILEF, smf + 3 * TILEF };
    int tid = threadIdx.x;
    int lane = tid & 31, wid = tid >> 5;
    int wm = (wid & 3) * 32;
    int wn = (wid >> 2) * 64;
    int g = lane >> 2, c = lane & 3;
    int rowBase = blockIdx.y * 128, colBase = blockIdx.x * 128;

    int srow[4], sseg[4], sb[4], st[4];
#pragma unroll
    for (int u = 0; u < 4; u++) {
        int f = tid + 256 * u;
        srow[u] = f >> 3;
        sseg[u] = f & 7;
        int grow = rowBase + srow[u];
        sb[u] = grow / T_;
        st[u] = grow - sb[u] * T_;
    }

    float acc[2][8][4];
#pragma unroll
    for (int i = 0; i < 2; i++)
#pragma unroll
        for (int j = 0; j < 8; j++)
#pragma unroll
            for (int q = 0; q < 4; q++) acc[i][j][q] = 0.f;

    const int NT = 11 * 16;
    // stage iter 0 (tap 0, kt 0)
#pragma unroll
    for (int u = 0; u < 4; u++) {
        int src = st[u] - 5;
        bool ok = (unsigned)src < (unsigned)T_;
        cp16(smem_u32(Abuf[0] + srow[u] * LDW + sseg[u] * 4),
             vm + ((size_t)(sb[u] * T_ + (ok ? src : 0)) * D_ + sseg[u] * 4), ok);
        cp16(smem_u32(Bbuf[0] + srow[u] * LDW + sseg[u] * 4),
             g_kwt + ((size_t)(colBase + srow[u]) * D_ + sseg[u] * 4), true);
    }
    CP_COMMIT();

    for (int ti = 0; ti < NT; ti++) {
        int buf = ti & 1;
        if (ti + 1 < NT) {
            int nb = buf ^ 1;
            int tap = (ti + 1) >> 4, kt = (ti + 1) & 15;
            const float* Bg = g_kwt + (size_t)tap * D_ * D_ + (size_t)colBase * D_ + kt * 32;
#pragma unroll
            for (int u = 0; u < 4; u++) {
                int src = st[u] + tap - 5;
                bool ok = (unsigned)src < (unsigned)T_;
                cp16(smem_u32(Abuf[nb] + srow[u] * LDW + sseg[u] * 4),
                     vm + ((size_t)(sb[u] * T_ + (ok ? src : 0)) * D_ + kt * 32 + sseg[u] * 4), ok);
                cp16(smem_u32(Bbuf[nb] + srow[u] * LDW + sseg[u] * 4),
                     Bg + (size_t)srow[u] * D_ + sseg[u] * 4, true);
            }
            CP_COMMIT();
            CP_WAIT1();
        } else {
            CP_WAIT0();
        }
        __syncthreads();
        const float* As = Abuf[buf];
        const float* Bs = Bbuf[buf];

        uint32_t af[2][2][8];
#pragma unroll
        for (int mt = 0; mt < 2; mt++)
#pragma unroll
            for (int rr = 0; rr < 2; rr++) {
                const float* ap = As + (wm + mt * 16 + g + rr * 8) * LDW + c * 8;
                float4 v0 = *(const float4*)ap;
                float4 v1 = *(const float4*)(ap + 4);
                af[mt][rr][0] = __float_as_uint(v0.x); af[mt][rr][1] = __float_as_uint(v0.y);
                af[mt][rr][2] = __float_as_uint(v0.z); af[mt][rr][3] = __float_as_uint(v0.w);
                af[mt][rr][4] = __float_as_uint(v1.x); af[mt][rr][5] = __float_as_uint(v1.y);
                af[mt][rr][6] = __float_as_uint(v1.z); af[mt][rr][7] = __float_as_uint(v1.w);
            }
#pragma unroll
        for (int nt = 0; nt < 8; nt++) {
            const float* bp = Bs + (wn + nt * 8 + g) * LDW + c * 8;
            float4 w0 = *(const float4*)bp;
            float4 w1 = *(const float4*)(bp + 4);
            uint32_t bf[8];
            bf[0] = __float_as_uint(w0.x); bf[1] = __float_as_uint(w0.y);
            bf[2] = __float_as_uint(w0.z); bf[3] = __float_as_uint(w0.w);
            bf[4] = __float_as_uint(w1.x); bf[5] = __float_as_uint(w1.y);
            bf[6] = __float_as_uint(w1.z); bf[7] = __float_as_uint(w1.w);
#pragma unroll
            for (int ks = 0; ks < 4; ks++) {
                MMA4(acc[0][nt], af[0][0][2*ks], af[0][1][2*ks],
                     af[0][0][2*ks+1], af[0][1][2*ks+1], bf[2*ks], bf[2*ks+1]);
                MMA4(acc[1][nt], af[1][0][2*ks], af[1][1][2*ks],
                     af[1][0][2*ks+1], af[1][1][2*ks+1], bf[2*ks], bf[2*ks+1]);
            }
        }
        __syncthreads();
    }

    // epilogue: out = (acc + v*m) * m   (natural layout)
#pragma unroll
    for (int mt = 0; mt < 2; mt++) {
#pragma unroll
        for (int nt = 0; nt < 8; nt++) {
            int cb = colBase + wn + nt * 8 + 2 * c;
#pragma unroll
            for (int half = 0; half < 2; half++) {
                int r = rowBase + wm + mt * 16 + g + half * 8;
                float m = masks[r];
                float v0 = qkv[(size_t)r * QKVW + 1024 + cb];
                float v1 = qkv[(size_t)r * QKVW + 1024 + cb + 1];
                float o0 = (acc[mt][nt][half * 2 + 0] + v0 * m) * m;
                float o1 = (acc[mt][nt][half * 2 + 1] + v1 * m) * m;
                *(float2*)(out + (size_t)r * D_ + cb) = make_float2(o0, o1);
            }
        }
    }
}

// ---------------- fused attention: scores + softmax + ctx -------------------
#define QT 32
#define SCPAD 224
#define ATT_SMEM ((QT*132 + QT*132 + QT*SCPAD)*4)
__global__ void __launch_bounds__(256)
att_kernel(const float* __restrict__ qkv, const float* __restrict__ masks,
           float* __restrict__ ctx) {
    extern __shared__ float smf[];
    float* Qs = smf;                 // [QT][132]
    float* Ks = smf + QT * 132;      // [QT][132]
    float* Sc = smf + 2 * QT * 132;  // [QT][SCPAD]
    int tid = threadIdx.x;
    int bh = blockIdx.y;
    int b = bh >> 2, h = bh & 3;
    int qbase = blockIdx.x * QT;
    int nq = T_ - qbase; if (nq > QT) nq = QT;
    const int qoff = h * DK_;
    const int koff = D_ + h * DK_;
    const int voff = 1024 + h * DK_;

    for (int f = tid; f < QT * 32; f += 256) {
        int row = f >> 5, seg = f & 31;
        float4 v = make_float4(0.f, 0.f, 0.f, 0.f);
        if (row < nq)
            v = *(const float4*)(qkv + (size_t)(b * T_ + qbase + row) * QKVW + qoff + seg * 4);
        *(float4*)(Qs + row * 132 + seg * 4) = v;
    }
    __syncthreads();

    int tx = tid & 15, ty = tid >> 4;
    const float scale = 0.08838834764831845f;
    for (int kbase = 0; kbase < T_; kbase += 32) {
        int nk2 = T_ - kbase; if (nk2 > 32) nk2 = 32;
        for (int f = tid; f < 32 * 32; f += 256) {
            int row = f >> 5, seg = f & 31;
            float4 v = make_float4(0.f, 0.f, 0.f, 0.f);
            if (row < nk2)
                v = *(const float4*)(qkv + (size_t)(b * T_ + kbase + row) * QKVW + koff + seg * 4);
            *(float4*)(Ks + row * 132 + seg * 4) = v;
        }
        __syncthreads();
        float acc[2][2] = {};
        const float* q0p = Qs + (ty * 2 + 0) * 132;
        const float* q1p = Qs + (ty * 2 + 1) * 132;
        const float* k0p = Ks + (tx * 2 + 0) * 132;
        const float* k1p = Ks + (tx * 2 + 1) * 132;
#pragma unroll 4
        for (int d = 0; d < DK_; d++) {
            float q0 = q0p[d], q1 = q1p[d];
            float k0 = k0p[d], k1 = k1p[d];
            acc[0][0] += q0 * k0; acc[0][1] += q0 * k1;
            acc[1][0] += q1 * k0; acc[1][1] += q1 * k1;
        }
#pragma unroll
        for (int i = 0; i < 2; i++) {
#pragma unroll
            for (int j = 0; j < 2; j++) {
                int kc = kbase + tx * 2 + j;
                if (kc < T_) {
                    float s = acc[i][j] * scale;
                    if (masks[b * T_ + kc] <= 0.f) s = -3.0e38f;
                    Sc[(ty * 2 + i) * SCPAD + kc] = s;
                }
            }
        }
        __syncthreads();
    }

    int lane = tid & 31, wrp = tid >> 5;
#pragma unroll
    for (int i = 0; i < 4; i++) {
        int row = wrp * 4 + i;
        float* p = Sc + row * SCPAD;
        float mx = -3.4e38f;
        for (int k = lane; k < T_; k += 32) mx = fmaxf(mx, p[k]);
#pragma unroll
        for (int o = 16; o; o >>= 1) mx = fmaxf(mx, __shfl_xor_sync(~0u, mx, o));
        float sum = 0.f;
        for (int k = lane; k < T_; k += 32) {
            float e = expf(p[k] - mx);
            p[k] = e;
            sum += e;
        }
#pragma unroll
        for (int o = 16; o; o >>= 1) sum += __shfl_xor_sync(~0u, sum, o);
        float inv = 1.f / sum;
        for (int k = lane; k < T_; k += 32) p[k] *= inv;
    }
    __syncthreads();

    int c = tid & 127;
    int rg = (tid >> 7) * 16;
    float acc[16];
#pragma unroll
    for (int i = 0; i < 16; i++) acc[i] = 0.f;
    for (int k = 0; k < T_; k++) {
        float vk = qkv[(size_t)(b * T_ + k) * QKVW + voff + c];
#pragma unroll
        for (int i = 0; i < 16; i++)
            acc[i] += Sc[(rg + i) * SCPAD + k] * vk;
    }
    int pc = pcol(h * DK_ + c);   // ctx stored K-permuted for out-proj GEMM
#pragma unroll
    for (int i = 0; i < 16; i++) {
        int r = qbase + rg + i;
        if (r < T_)
            ctx[(size_t)(b * T_ + r) * D_ + pc] = rna_tf32(acc[i]);
    }
}

// ---------------- launch ------------------------------------------------------
extern "C" void kernel_launch(void* const* d_in, const int* in_sizes, int n_in,
                              void* d_out, int out_size) {
    const float* x     = (const float*)d_in[0];
    const float* masks = (const float*)d_in[1];
    const float* ln0_w = (const float*)d_in[2];
    const float* ln0_b = (const float*)d_in[3];
    const float* ln1_w = (const float*)d_in[4];
    const float* ln1_b = (const float*)d_in[5];
    const float* qkv_w = (const float*)d_in[6];
    const float* qkv_b = (const float*)d_in[7];
    const float* out_w = (const float*)d_in[8];
    const float* out_b = (const float*)d_in[9];
    const float* fsmn_w= (const float*)d_in[10];
    const float* w1    = (const float*)d_in[11];
    const float* b1    = (const float*)d_in[12];
    const float* w2    = (const float*)d_in[13];
    const float* b2    = (const float*)d_in[14];
    float* out = (float*)d_out;

    float *h, *qkv, *vm, *fsmn, *ctx, *x1, *mid;
    float *qkv_wt, *out_wt, *w1t, *w2t;
    cudaGetSymbolAddress((void**)&h,      g_h);
    cudaGetSymbolAddress((void**)&qkv,    g_qkv);
    cudaGetSymbolAddress((void**)&vm,     g_vm);
    cudaGetSymbolAddress((void**)&fsmn,   g_fsmn);
    cudaGetSymbolAddress((void**)&ctx,    g_ctx);
    cudaGetSymbolAddress((void**)&x1,     g_x1);
    cudaGetSymbolAddress((void**)&mid,    g_mid);
    cudaGetSymbolAddress((void**)&qkv_wt, g_qkv_wt);
    cudaGetSymbolAddress((void**)&out_wt, g_out_wt);
    cudaGetSymbolAddress((void**)&w1t,    g_w1t);
    cudaGetSymbolAddress((void**)&w2t,    g_w2t);

    cudaFuncSetAttribute(tgemm, cudaFuncAttributeMaxDynamicSharedMemorySize, DSMEM_BYTES);
    cudaFuncSetAttribute(tconv, cudaFuncAttributeMaxDynamicSharedMemorySize, DSMEM_BYTES);
    cudaFuncSetAttribute(att_kernel, cudaFuncAttributeMaxDynamicSharedMemorySize, ATT_SMEM);

    // weight prep (tf32-rounded, [N,K] K-permuted layouts)
    transpose_rna<<<dim3(QKVW / 32, D_ / 32), dim3(32, 8)>>>(qkv_w, qkv_wt, D_, QKVW);
    transpose_rna<<<dim3(D_ / 32, D_ / 32), dim3(32, 8)>>>(out_w, out_wt, D_, D_);
    transpose_rna<<<dim3(2048 / 32, D_ / 32), dim3(32, 8)>>>(w1, w1t, D_, 2048);
    transpose_rna<<<dim3(D_ / 32, 2048 / 32), dim3(32, 8)>>>(w2, w2t, 2048, D_);
    kw_transpose<<<(11 * D_ * D_ + 255) / 256, 256>>>(fsmn_w);

    // LN0 (rounded, permuted output)
    ln_kernel<<<R_, 128>>>(x, ln0_w, ln0_b, h);

    // QKV (epi 5: also writes vm permuted for v columns)
    tgemm<<<dim3(QKVW / 128, R_ / 128), 256, DSMEM_BYTES>>>(h, qkv_wt, qkv_b, qkv,
                                                            QKVW, D_, 5, masks, vm);

    // FSMN conv
    tconv<<<dim3(D_ / 128, R_ / 128), 256, DSMEM_BYTES>>>(vm, qkv, masks, fsmn);

    // fused attention (ctx written permuted)
    att_kernel<<<dim3((T_ + QT - 1) / QT, B_ * H_), 256, ATT_SMEM>>>(qkv, masks, ctx);

    // out proj + fsmn + residual
    tgemm<<<dim3(D_ / 128, R_ / 128), 256, DSMEM_BYTES>>>(ctx, out_wt, out_b, x1,
                                                          D_, D_, 2, fsmn, (float*)x);
    // LN1 (permuted output)
    ln_kernel<<<R_, 128>>>(x1, ln1_w, ln1_b, h);

    // FFN (mid written permuted by epi 1)
    tgemm<<<dim3(2048 / 128, R_ / 128), 256, DSMEM_BYTES>>>(h, w1t, b1, mid,
                                                            2048, D_, 1, nullptr, nullptr);
    tgemm<<<dim3(D_ / 128, R_ / 128), 256, DSMEM_BYTES>>>(mid, w2t, b2, out,
                                                          D_, 2048, 3, x1, nullptr);
    (void)in_sizes; (void)n_in; (void)out_size;
}

// round 7
// speedup vs baseline: 1.4301x; 1.4301x over previous
#include <cuda_runtime.h>
#include <cuda_fp16.h>
#include <math.h>
#include <cstdint>

#define B_  64
#define T_  218
#define D_  512
#define R_  (B_*T_)      // 13952 = 109*128
#define H_  4
#define DK_ 128
#define QKVW (3*D_)      // 1536

// ---------------- scratch (device globals) ----------------------------------
__device__ __half g_h[R_*D_];                 // LN output (half)
__device__ float  g_qkv[R_*QKVW];             // fp32 (attention reads it)
__device__ __half g_vm[R_*D_];                // masked v (half)
__device__ float  g_fsmn[R_*D_];
__device__ float  g_scores[B_*H_*T_*T_];
__device__ __half g_ctx[R_*D_];               // attention context (half)
__device__ float  g_x1[R_*D_];
__device__ __half g_mid[R_*2048];             // ffn hidden (half)
__device__ __half g_qkv_wt[QKVW*D_];          // [N,K] half
__device__ __half g_out_wt[D_*D_];
__device__ __half g_w1t[2048*D_];
__device__ __half g_w2t[D_*2048];
__device__ __half g_kwt[11*D_*D_];            // [tap][dout][din]

// ---------------- helpers ----------------------------------------------------
__device__ __forceinline__ uint32_t smem_u32(const void* p) {
    uint32_t a;
    asm("{ .reg .u64 t; cvta.to.shared.u64 t, %1; cvt.u32.u64 %0, t; }" : "=r"(a) : "l"(p));
    return a;
}
__device__ __forceinline__ void cp16(uint32_t dst, const void* src, bool pred) {
    int sz = pred ? 16 : 0;
    asm volatile("cp.async.ca.shared.global [%0], [%1], 16, %2;"
                 :: "r"(dst), "l"(src), "r"(sz) : "memory");
}
#define CP_COMMIT() asm volatile("cp.async.commit_group;" ::: "memory")
#define CP_WAIT1()  asm volatile("cp.async.wait_group 1;" ::: "memory")
#define CP_WAIT0()  asm volatile("cp.async.wait_group 0;" ::: "memory")

// fp16 mma m16n8k16, fp32 accumulate
#define MMAH(d, a0, a1, a2, a3, b0, b1) \
    asm volatile("mma.sync.aligned.m16n8k16.row.col.f32.f16.f16.f32 " \
                 "{%0,%1,%2,%3},{%4,%5,%6,%7},{%8,%9},{%0,%1,%2,%3};" \
                 : "+f"((d)[0]), "+f"((d)[1]), "+f"((d)[2]), "+f"((d)[3]) \
                 : "r"(a0), "r"(a1), "r"(a2), "r"(a3), "r"(b0), "r"(b1))

#define LDWH 40                        // halfs per smem row (80B); conflict-free
#define TILEH (128*LDWH)               // halfs per tile buffer
#define DSMEM_BYTES (4*TILEH*2)        // A0,B0,A1,B1 = 40960 B

// ---------------- weight transpose (fp32 [K,N] -> half [N,K]) --------------
__global__ void transpose_h(const float* __restrict__ src, __half* __restrict__ dst,
                            int Kd, int Nd) {
    __shared__ float t[32][33];
    int k0 = blockIdx.y * 32, n0 = blockIdx.x * 32;
    int x = threadIdx.x, y = threadIdx.y;   // (32,8)
#pragma unroll
    for (int i = 0; i < 32; i += 8)
        t[y + i][x] = src[(size_t)(k0 + y + i) * Nd + n0 + x];
    __syncthreads();
#pragma unroll
    for (int i = 0; i < 32; i += 8)
        dst[(size_t)(n0 + y + i) * Kd + k0 + x] = __float2half(t[x][y + i]);
}

__global__ void kw_transpose(const float* __restrict__ fw) {
    int idx = blockIdx.x * 256 + threadIdx.x;
    if (idx >= 11 * D_ * D_) return;
    int tap = idx / (D_ * D_);
    int rem = idx % (D_ * D_);
    int dout = rem / D_;
    int din = rem % D_;
    g_kwt[idx] = __float2half(fw[((size_t)dout * D_ + din) * 11 + tap]);
}

// ---------------- vm = half(v * mask) ---------------------------------------
__global__ void vm_kernel(const float* __restrict__ qkv, const float* __restrict__ masks,
                          __half* __restrict__ vm) {
    int idx = blockIdx.x * 256 + threadIdx.x;
    int r = idx >> 9, d = idx & 511;
    vm[idx] = __float2half(qkv[(size_t)r * QKVW + 1024 + d] * masks[r]);
}

// ---------------- layer norm (half output) ----------------------------------
__global__ void ln_kernel(const float* __restrict__ x, const float* __restrict__ w,
                          const float* __restrict__ b, __half* __restrict__ out) {
    int row = blockIdx.x;
    const float* xr = x + (size_t)row * D_;
    __half* orow = out + (size_t)row * D_;
    float v[4];
    float s = 0.f, sq = 0.f;
#pragma unroll
    for (int i = 0; i < 4; i++) {
        v[i] = xr[threadIdx.x + i * 128];
        s += v[i]; sq += v[i] * v[i];
    }
    __shared__ float sm[8];
#pragma unroll
    for (int o = 16; o; o >>= 1) {
        s  += __shfl_xor_sync(~0u, s, o);
        sq += __shfl_xor_sync(~0u, sq, o);
    }
    int lane = threadIdx.x & 31, wid = threadIdx.x >> 5;
    if (lane == 0) { sm[wid] = s; sm[4 + wid] = sq; }
    __syncthreads();
    if (threadIdx.x == 0) {
        float S = sm[0] + sm[1] + sm[2] + sm[3];
        float SQ = sm[4] + sm[5] + sm[6] + sm[7];
        float mean = S * (1.f / D_);
        float var = SQ * (1.f / D_) - mean * mean;
        sm[0] = mean;
        sm[1] = rsqrtf(var + 1e-5f);
    }
    __syncthreads();
    float mean = sm[0], inv = sm[1];
#pragma unroll
    for (int i = 0; i < 4; i++) {
        int c = threadIdx.x + i * 128;
        orow[c] = __float2half((v[i] - mean) * inv * w[c] + b[c]);
    }
}

// ---------------- fp16 mma.sync GEMM (R3 structure, half data) --------------
// C[M,N] = A[M,K] @ Bt[N,K]^T + bias. A,Bt half.
// epi: 0=bias->Cf; 1=bias+relu->Ch (half, mid); 2=bias+add1+add2->Cf; 3=bias+add1->Cf
__global__ void __launch_bounds__(256)
hgemm(const __half* __restrict__ A, const __half* __restrict__ Bt,
      const float* __restrict__ bias, float* __restrict__ Cf, __half* __restrict__ Ch,
      int N, int K, int epi,
      const float* __restrict__ add1, const float* __restrict__ add2) {
    extern __shared__ __half smh[];
    __half* Abuf[2] = { smh,         smh + 2 * TILEH };
    __half* Bbuf[2] = { smh + TILEH, smh + 3 * TILEH };
    int tid = threadIdx.x;
    int lane = tid & 31, wid = tid >> 5;
    int wm = (wid & 3) * 32;
    int wn = (wid >> 2) * 64;
    int g = lane >> 2, c = lane & 3;
    int rowBase = blockIdx.y * 128, colBase = blockIdx.x * 128;

    // staging: tile = 128 rows x 32 halfs (64B) = 4 chunks/row; 512 chunks; 2/thread
    int srow[2], sseg[2];
#pragma unroll
    for (int u = 0; u < 2; u++) {
        int f = tid + 256 * u;
        srow[u] = f >> 2;
        sseg[u] = f & 3;
    }

    float acc[2][8][4];
#pragma unroll
    for (int i = 0; i < 2; i++)
#pragma unroll
        for (int j = 0; j < 8; j++)
#pragma unroll
            for (int q = 0; q < 4; q++) acc[i][j][q] = 0.f;

    int nk = K >> 5;
    const __half* Arow = A + (size_t)rowBase * K;
    const __half* Brow = Bt + (size_t)colBase * K;

#pragma unroll
    for (int u = 0; u < 2; u++) {
        cp16(smem_u32(Abuf[0] + srow[u] * LDWH + sseg[u] * 8),
             Arow + (size_t)srow[u] * K + sseg[u] * 8, true);
        cp16(smem_u32(Bbuf[0] + srow[u] * LDWH + sseg[u] * 8),
             Brow + (size_t)srow[u] * K + sseg[u] * 8, true);
    }
    CP_COMMIT();

    for (int kt = 0; kt < nk; kt++) {
        int buf = kt & 1;
        if (kt + 1 < nk) {
            int nb = buf ^ 1;
            const __half* Ag = Arow + (size_t)(kt + 1) * 32;
            const __half* Bg = Brow + (size_t)(kt + 1) * 32;
#pragma unroll
            for (int u = 0; u < 2; u++) {
                cp16(smem_u32(Abuf[nb] + srow[u] * LDWH + sseg[u] * 8),
                     Ag + (size_t)srow[u] * K + sseg[u] * 8, true);
                cp16(smem_u32(Bbuf[nb] + srow[u] * LDWH + sseg[u] * 8),
                     Bg + (size_t)srow[u] * K + sseg[u] * 8, true);
            }
            CP_COMMIT();
            CP_WAIT1();
        } else {
            CP_WAIT0();
        }
        __syncthreads();
        const uint32_t* As = (const uint32_t*)Abuf[buf];   // 20 words per row
        const uint32_t* Bs = (const uint32_t*)Bbuf[buf];
#pragma unroll
        for (int ks = 0; ks < 2; ks++) {                   // two k16 steps
            int kw = ks * 8;                                // word offset in row
            uint32_t a[2][4];
#pragma unroll
            for (int mt = 0; mt < 2; mt++) {
                const uint32_t* ap = As + (wm + mt * 16 + g) * 20 + kw;
                const uint32_t* ap8 = ap + 8 * 20;
                a[mt][0] = ap[c];
                a[mt][1] = ap8[c];
                a[mt][2] = ap[c + 4];
                a[mt][3] = ap8[c + 4];
            }
#pragma unroll
            for (int nt = 0; nt < 8; nt++) {
                const uint32_t* bp = Bs + (wn + nt * 8 + g) * 20 + kw;
                uint32_t b0 = bp[c];
                uint32_t b1 = bp[c + 4];
                MMAH(acc[0][nt], a[0][0], a[0][1], a[0][2], a[0][3], b0, b1);
                MMAH(acc[1][nt], a[1][0], a[1][1], a[1][2], a[1][3], b0, b1);
            }
        }
        __syncthreads();
    }

    // epilogue
#pragma unroll
    for (int mt = 0; mt < 2; mt++) {
#pragma unroll
        for (int nt = 0; nt < 8; nt++) {
            int cb = colBase + wn + nt * 8 + 2 * c;
            float bs0 = bias[cb], bs1 = bias[cb + 1];
#pragma unroll
            for (int half = 0; half < 2; half++) {
                int r = rowBase + wm + mt * 16 + g + half * 8;
                float v0 = acc[mt][nt][half * 2 + 0] + bs0;
                float v1 = acc[mt][nt][half * 2 + 1] + bs1;
                if (epi == 1) {
                    __half2 hv = __floats2half2_rn(fmaxf(v0, 0.f), fmaxf(v1, 0.f));
                    *(__half2*)(Ch + (size_t)r * N + cb) = hv;
                    continue;
                } else if (epi == 2) {
                    size_t id = (size_t)r * 512 + cb;
                    v0 += add1[id] + add2[id];
                    v1 += add1[id + 1] + add2[id + 1];
                } else if (epi == 3) {
                    size_t id = (size_t)r * 512 + cb;
                    v0 += add1[id];
                    v1 += add1[id + 1];
                }
                *(float2*)(Cf + (size_t)r * N + cb) = make_float2(v0, v1);
            }
        }
    }
}

// ---------------- FSMN conv via fp16 mma: 11 shifted GEMMs ------------------
__global__ void __launch_bounds__(256)
hconv(const __half* __restrict__ vm, const float* __restrict__ qkv,
      const float* __restrict__ masks, float* __restrict__ out) {
    extern __shared__ __half smh[];
    __half* Abuf[2] = { smh,         smh + 2 * TILEH };
    __half* Bbuf[2] = { smh + TILEH, smh + 3 * TILEH };
    int tid = threadIdx.x;
    int lane = tid & 31, wid = tid >> 5;
    int wm = (wid & 3) * 32;
    int wn = (wid >> 2) * 64;
    int g = lane >> 2, c = lane & 3;
    int rowBase = blockIdx.y * 128, colBase = blockIdx.x * 128;

    int srow[2], sseg[2], sb[2], st[2];
#pragma unroll
    for (int u = 0; u < 2; u++) {
        int f = tid + 256 * u;
        srow[u] = f >> 2;
        sseg[u] = f & 3;
        int grow = rowBase + srow[u];
        sb[u] = grow / T_;
        st[u] = grow - sb[u] * T_;
    }

    float acc[2][8][4];
#pragma unroll
    for (int i = 0; i < 2; i++)
#pragma unroll
        for (int j = 0; j < 8; j++)
#pragma unroll
            for (int q = 0; q < 4; q++) acc[i][j][q] = 0.f;

    const int NT = 11 * 16;
    // stage iter 0 (tap 0, kt 0)
#pragma unroll
    for (int u = 0; u < 2; u++) {
        int src = st[u] - 5;
        bool ok = (unsigned)src < (unsigned)T_;
        cp16(smem_u32(Abuf[0] + srow[u] * LDWH + sseg[u] * 8),
             vm + ((size_t)(sb[u] * T_ + (ok ? src : 0)) * D_ + sseg[u] * 8), ok);
        cp16(smem_u32(Bbuf[0] + srow[u] * LDWH + sseg[u] * 8),
             g_kwt + ((size_t)(colBase + srow[u]) * D_ + sseg[u] * 8), true);
    }
    CP_COMMIT();

    for (int ti = 0; ti < NT; ti++) {
        int buf = ti & 1;
        if (ti + 1 < NT) {
            int nb = buf ^ 1;
            int tap = (ti + 1) >> 4, kt = (ti + 1) & 15;
            const __half* Bg = g_kwt + (size_t)tap * D_ * D_ + (size_t)colBase * D_ + kt * 32;
#pragma unroll
            for (int u = 0; u < 2; u++) {
                int src = st[u] + tap - 5;
                bool ok = (unsigned)src < (unsigned)T_;
                cp16(smem_u32(Abuf[nb] + srow[u] * LDWH + sseg[u] * 8),
                     vm + ((size_t)(sb[u] * T_ + (ok ? src : 0)) * D_ + kt * 32 + sseg[u] * 8), ok);
                cp16(smem_u32(Bbuf[nb] + srow[u] * LDWH + sseg[u] * 8),
                     Bg + (size_t)srow[u] * D_ + sseg[u] * 8, true);
            }
            CP_COMMIT();
            CP_WAIT1();
        } else {
            CP_WAIT0();
        }
        __syncthreads();
        const uint32_t* As = (const uint32_t*)Abuf[buf];
        const uint32_t* Bs = (const uint32_t*)Bbuf[buf];
#pragma unroll
        for (int ks = 0; ks < 2; ks++) {
            int kw = ks * 8;
            uint32_t a[2][4];
#pragma unroll
            for (int mt = 0; mt < 2; mt++) {
                const uint32_t* ap = As + (wm + mt * 16 + g) * 20 + kw;
                const uint32_t* ap8 = ap + 8 * 20;
                a[mt][0] = ap[c];
                a[mt][1] = ap8[c];
                a[mt][2] = ap[c + 4];
                a[mt][3] = ap8[c + 4];
            }
#pragma unroll
            for (int nt = 0; nt < 8; nt++) {
                const uint32_t* bp = Bs + (wn + nt * 8 + g) * 20 + kw;
                uint32_t b0 = bp[c];
                uint32_t b1 = bp[c + 4];
                MMAH(acc[0][nt], a[0][0], a[0][1], a[0][2], a[0][3], b0, b1);
                MMAH(acc[1][nt], a[1][0], a[1][1], a[1][2], a[1][3], b0, b1);
            }
        }
        __syncthreads();
    }

    // epilogue: out = (acc + v*m) * m
#pragma unroll
    for (int mt = 0; mt < 2; mt++) {
#pragma unroll
        for (int nt = 0; nt < 8; nt++) {
            int cb = colBase + wn + nt * 8 + 2 * c;
#pragma unroll
            for (int half = 0; half < 2; half++) {
                int r = rowBase + wm + mt * 16 + g + half * 8;
                float m = masks[r];
                float v0 = qkv[(size_t)r * QKVW + 1024 + cb];
                float v1 = qkv[(size_t)r * QKVW + 1024 + cb + 1];
                float o0 = (acc[mt][nt][half * 2 + 0] + v0 * m) * m;
                float o1 = (acc[mt][nt][half * 2 + 1] + v1 * m) * m;
                *(float2*)(out + (size_t)r * D_ + cb) = make_float2(o0, o1);
            }
        }
    }
}

// ---------------- attention (fp32, R3-proven kernels) ------------------------
__global__ void scores_kernel(const float* __restrict__ qkv, const float* __restrict__ masks,
                              float* __restrict__ scores) {
    int bh = blockIdx.z;
    int b = bh >> 2, h = bh & 3;
    int qbase = blockIdx.y * 32;
    int kbase = blockIdx.x * 32;
    __shared__ float Qs[32][33];
    __shared__ float Ks[32][33];
    int tid = threadIdx.x;
    int tx = tid & 15, ty = tid >> 4;
    float acc[2][2] = {};
    const int qoff = h * DK_;
    const int koff = D_ + h * DK_;
    for (int kc = 0; kc < DK_; kc += 32) {
#pragma unroll
        for (int i = 0; i < 4; i++) {
            int e = tid + 256 * i;
            int rr = e >> 5, cc = e & 31;
            int qr = qbase + rr;
            Qs[rr][cc] = (qr < T_) ? qkv[(size_t)(b * T_ + qr) * QKVW + qoff + kc + cc] : 0.f;
            int kr = kbase + rr;
            Ks[rr][cc] = (kr < T_) ? qkv[(size_t)(b * T_ + kr) * QKVW + koff + kc + cc] : 0.f;
        }
        __syncthreads();
#pragma unroll
        for (int kk = 0; kk < 32; kk++) {
            float q0 = Qs[ty * 2 + 0][kk], q1 = Qs[ty * 2 + 1][kk];
            float k0 = Ks[tx * 2 + 0][kk], k1 = Ks[tx * 2 + 1][kk];
            acc[0][0] += q0 * k0; acc[0][1] += q0 * k1;
            acc[1][0] += q1 * k0; acc[1][1] += q1 * k1;
        }
        __syncthreads();
    }
    const float scale = 0.08838834764831845f;
#pragma unroll
    for (int i = 0; i < 2; i++) {
        int r = qbase + ty * 2 + i;
        if (r >= T_) continue;
#pragma unroll
        for (int j = 0; j < 2; j++) {
            int c = kbase + tx * 2 + j;
            if (c >= T_) continue;
            float s = acc[i][j] * scale;
            if (masks[b * T_ + c] <= 0.f) s = -3.0e38f;
            scores[((size_t)bh * T_ + r) * T_ + c] = s;
        }
    }
}

__global__ void softmax_kernel(float* __restrict__ scores) {
    float* p = scores + (size_t)blockIdx.x * T_;
    int tid = threadIdx.x;
    float v = (tid < T_) ? p[tid] : -3.4e38f;
    __shared__ float red[8];
    float m = v;
#pragma unroll
    for (int o = 16; o; o >>= 1) m = fmaxf(m, __shfl_xor_sync(~0u, m, o));
    if ((tid & 31) == 0) red[tid >> 5] = m;
    __syncthreads();
    if (tid < 8) {
        float t = red[tid];
#pragma unroll
        for (int o = 4; o; o >>= 1) t = fmaxf(t, __shfl_xor_sync(0xff, t, o));
        red[tid] = t;
    }
    __syncthreads();
    float mx = red[0];
    float e = (tid < T_) ? expf(v - mx) : 0.f;
    __syncthreads();
    float s = e;
#pragma unroll
    for (int o = 16; o; o >>= 1) s += __shfl_xor_sync(~0u, s, o);
    if ((tid & 31) == 0) red[tid >> 5] = s;
    __syncthreads();
    if (tid < 8) {
        float t = red[tid];
#pragma unroll
        for (int o = 4; o; o >>= 1) t += __shfl_xor_sync(0xff, t, o);
        red[tid] = t;
    }
    __syncthreads();
    float inv = 1.f / red[0];
    if (tid < T_) p[tid] = e * inv;
}

__global__ void ctx_kernel(const float* __restrict__ scores, const float* __restrict__ qkv,
                           __half* __restrict__ ctx) {
    int bh = blockIdx.y;
    int b = bh >> 2, h = bh & 3;
    int t0 = blockIdx.x * 16;
    int nt = T_ - t0; if (nt > 16) nt = 16;
    __shared__ float at[16][T_];
    int tid = threadIdx.x;
    for (int e = tid; e < 16 * T_; e += 128) {
        int tt = e / T_, k = e % T_;
        at[tt][k] = (tt < nt) ? scores[((size_t)bh * T_ + t0 + tt) * T_ + k] : 0.f;
    }
    __syncthreads();
    float acc[16] = {};
    const int voff = 1024 + h * DK_;
    for (int k = 0; k < T_; k++) {
        float vk = qkv[(size_t)(b * T_ + k) * QKVW + voff + tid];
#pragma unroll
        for (int tt = 0; tt < 16; tt++) acc[tt] += at[tt][k] * vk;
    }
    for (int tt = 0; tt < nt; tt++)
        ctx[(size_t)(b * T_ + t0 + tt) * D_ + h * DK_ + tid] = __float2half(acc[tt]);
}

// ---------------- launch ------------------------------------------------------
extern "C" void kernel_launch(void* const* d_in, const int* in_sizes, int n_in,
                              void* d_out, int out_size) {
    const float* x     = (const float*)d_in[0];
    const float* masks = (const float*)d_in[1];
    const float* ln0_w = (const float*)d_in[2];
    const float* ln0_b = (const float*)d_in[3];
    const float* ln1_w = (const float*)d_in[4];
    const float* ln1_b = (const float*)d_in[5];
    const float* qkv_w = (const float*)d_in[6];
    const float* qkv_b = (const float*)d_in[7];
    const float* out_w = (const float*)d_in[8];
    const float* out_b = (const float*)d_in[9];
    const float* fsmn_w= (const float*)d_in[10];
    const float* w1    = (const float*)d_in[11];
    const float* b1    = (const float*)d_in[12];
    const float* w2    = (const float*)d_in[13];
    const float* b2    = (const float*)d_in[14];
    float* out = (float*)d_out;

    __half *h, *vm, *ctx, *mid, *qkv_wt, *out_wt, *w1t, *w2t;
    float *qkv, *fsmn, *scores, *x1;
    cudaGetSymbolAddress((void**)&h,      g_h);
    cudaGetSymbolAddress((void**)&qkv,    g_qkv);
    cudaGetSymbolAddress((void**)&vm,     g_vm);
    cudaGetSymbolAddress((void**)&fsmn,   g_fsmn);
    cudaGetSymbolAddress((void**)&scores, g_scores);
    cudaGetSymbolAddress((void**)&ctx,    g_ctx);
    cudaGetSymbolAddress((void**)&x1,     g_x1);
    cudaGetSymbolAddress((void**)&mid,    g_mid);
    cudaGetSymbolAddress((void**)&qkv_wt, g_qkv_wt);
    cudaGetSymbolAddress((void**)&out_wt, g_out_wt);
    cudaGetSymbolAddress((void**)&w1t,    g_w1t);
    cudaGetSymbolAddress((void**)&w2t,    g_w2t);

    cudaFuncSetAttribute(hgemm, cudaFuncAttributeMaxDynamicSharedMemorySize, DSMEM_BYTES);
    cudaFuncSetAttribute(hconv, cudaFuncAttributeMaxDynamicSharedMemorySize, DSMEM_BYTES);

    // weight prep (half, [N,K])
    transpose_h<<<dim3(QKVW / 32, D_ / 32), dim3(32, 8)>>>(qkv_w, qkv_wt, D_, QKVW);
    transpose_h<<<dim3(D_ / 32, D_ / 32), dim3(32, 8)>>>(out_w, out_wt, D_, D_);
    transpose_h<<<dim3(2048 / 32, D_ / 32), dim3(32, 8)>>>(w1, w1t, D_, 2048);
    transpose_h<<<dim3(D_ / 32, 2048 / 32), dim3(32, 8)>>>(w2, w2t, 2048, D_);
    kw_transpose<<<(11 * D_ * D_ + 255) / 256, 256>>>(fsmn_w);

    // LN0 -> half h
    ln_kernel<<<R_, 128>>>(x, ln0_w, ln0_b, h);

    // QKV
    hgemm<<<dim3(QKVW / 128, R_ / 128), 256, DSMEM_BYTES>>>(h, qkv_wt, qkv_b, qkv, nullptr,
                                                            QKVW, D_, 0, nullptr, nullptr);
    // masked v -> half
    vm_kernel<<<R_ * D_ / 256, 256>>>(qkv, masks, vm);

    // FSMN conv
    hconv<<<dim3(D_ / 128, R_ / 128), 256, DSMEM_BYTES>>>(vm, qkv, masks, fsmn);

    // attention
    scores_kernel<<<dim3(7, 7, B_ * H_), 256>>>(qkv, masks, scores);
    softmax_kernel<<<B_ * H_ * T_, 256>>>(scores);
    ctx_kernel<<<dim3((T_ + 15) / 16, B_ * H_), 128>>>(scores, qkv, ctx);

    // out proj + fsmn + residual -> x1
    hgemm<<<dim3(D_ / 128, R_ / 128), 256, DSMEM_BYTES>>>(ctx, out_wt, out_b, x1, nullptr,
                                                          D_, D_, 2, fsmn, x);
    // LN1 -> half h
    ln_kernel<<<R_, 128>>>(x1, ln1_w, ln1_b, h);

    // FFN
    hgemm<<<dim3(2048 / 128, R_ / 128), 256, DSMEM_BYTES>>>(h, w1t, b1, nullptr, mid,
                                                            2048, D_, 1, nullptr, nullptr);
    hgemm<<<dim3(D_ / 128, R_ / 128), 256, DSMEM_BYTES>>>(mid, w2t, b2, out, nullptr,
                                                          D_, 2048, 3, x1, nullptr);
    (void)in_sizes; (void)n_in; (void)out_size;
}

// round 8
// speedup vs baseline: 1.6288x; 1.1389x over previous
#include <cuda_runtime.h>
#include <cuda_fp16.h>
#include <math.h>
#include <cstdint>

#define B_  64
#define T_  218
#define D_  512
#define R_  (B_*T_)      // 13952 = 109*128
#define H_  4
#define DK_ 128
#define QKVW (3*D_)      // 1536

// ---------------- scratch (device globals) ----------------------------------
__device__ __half g_h[R_*D_];                 // LN output (half)
__device__ __half g_qkv[R_*QKVW];             // qkv (half)
__device__ __half g_vm[R_*D_];                // masked v (half)
__device__ float  g_fsmn[R_*D_];
__device__ float  g_scores[B_*H_*T_*T_];
__device__ __half g_ctx[R_*D_];               // attention context (half)
__device__ float  g_x1[R_*D_];
__device__ __half g_mid[R_*2048];             // ffn hidden (half)
__device__ __half g_qkv_wt[QKVW*D_];          // [N,K] half
__device__ __half g_out_wt[D_*D_];
__device__ __half g_w1t[2048*D_];
__device__ __half g_w2t[D_*2048];
__device__ __half g_kwt[11*D_*D_];            // [tap][dout][din]

// ---------------- helpers ----------------------------------------------------
__device__ __forceinline__ uint32_t smem_u32(const void* p) {
    uint32_t a;
    asm("{ .reg .u64 t; cvta.to.shared.u64 t, %1; cvt.u32.u64 %0, t; }" : "=r"(a) : "l"(p));
    return a;
}
__device__ __forceinline__ void cp16(uint32_t dst, const void* src, bool pred) {
    int sz = pred ? 16 : 0;
    asm volatile("cp.async.ca.shared.global [%0], [%1], 16, %2;"
                 :: "r"(dst), "l"(src), "r"(sz) : "memory");
}
#define CP_COMMIT() asm volatile("cp.async.commit_group;" ::: "memory")
#define CP_WAIT1()  asm volatile("cp.async.wait_group 1;" ::: "memory")
#define CP_WAIT0()  asm volatile("cp.async.wait_group 0;" ::: "memory")

#define MMAH(d, a0, a1, a2, a3, b0, b1) \
    asm volatile("mma.sync.aligned.m16n8k16.row.col.f32.f16.f16.f32 " \
                 "{%0,%1,%2,%3},{%4,%5,%6,%7},{%8,%9},{%0,%1,%2,%3};" \
                 : "+f"((d)[0]), "+f"((d)[1]), "+f"((d)[2]), "+f"((d)[3]) \
                 : "r"(a0), "r"(a1), "r"(a2), "r"(a3), "r"(b0), "r"(b1))

#define KT  64                          // K-chunk per stage
#define LDWH 72                         // halfs per smem row (144B), conflict-free
#define LDWW 36                         // words per smem row
#define TILEH (128*LDWH)                // halfs per tile buffer
#define DSMEM_BYTES (4*TILEH*2)         // A0,B0,A1,B1 = 73728 B

// ---------------- weight transpose (fp32 [K,N] -> half [N,K]) --------------
__global__ void transpose_h(const float* __restrict__ src, __half* __restrict__ dst,
                            int Kd, int Nd) {
    __shared__ float t[32][33];
    int k0 = blockIdx.y * 32, n0 = blockIdx.x * 32;
    int x = threadIdx.x, y = threadIdx.y;   // (32,8)
#pragma unroll
    for (int i = 0; i < 32; i += 8)
        t[y + i][x] = src[(size_t)(k0 + y + i) * Nd + n0 + x];
    __syncthreads();
#pragma unroll
    for (int i = 0; i < 32; i += 8)
        dst[(size_t)(n0 + y + i) * Kd + k0 + x] = __float2half(t[x][y + i]);
}

__global__ void kw_transpose(const float* __restrict__ fw) {
    int idx = blockIdx.x * 256 + threadIdx.x;
    if (idx >= 11 * D_ * D_) return;
    int tap = idx / (D_ * D_);
    int rem = idx % (D_ * D_);
    int dout = rem / D_;
    int din = rem % D_;
    g_kwt[idx] = __float2half(fw[((size_t)dout * D_ + din) * 11 + tap]);
}

// ---------------- vm = v * mask (half) ---------------------------------------
__global__ void vm_kernel(const __half* __restrict__ qkv, const float* __restrict__ masks,
                          __half* __restrict__ vm) {
    int idx = blockIdx.x * 256 + threadIdx.x;
    int r = idx >> 9, d = idx & 511;
    vm[idx] = __float2half(__half2float(qkv[(size_t)r * QKVW + 1024 + d]) * masks[r]);
}

// ---------------- layer norm (half output) ----------------------------------
__global__ void ln_kernel(const float* __restrict__ x, const float* __restrict__ w,
                          const float* __restrict__ b, __half* __restrict__ out) {
    int row = blockIdx.x;
    const float* xr = x + (size_t)row * D_;
    __half* orow = out + (size_t)row * D_;
    float v[4];
    float s = 0.f, sq = 0.f;
#pragma unroll
    for (int i = 0; i < 4; i++) {
        v[i] = xr[threadIdx.x + i * 128];
        s += v[i]; sq += v[i] * v[i];
    }
    __shared__ float sm[8];
#pragma unroll
    for (int o = 16; o; o >>= 1) {
        s  += __shfl_xor_sync(~0u, s, o);
        sq += __shfl_xor_sync(~0u, sq, o);
    }
    int lane = threadIdx.x & 31, wid = threadIdx.x >> 5;
    if (lane == 0) { sm[wid] = s; sm[4 + wid] = sq; }
    __syncthreads();
    if (threadIdx.x == 0) {
        float S = sm[0] + sm[1] + sm[2] + sm[3];
        float SQ = sm[4] + sm[5] + sm[6] + sm[7];
        float mean = S * (1.f / D_);
        float var = SQ * (1.f / D_) - mean * mean;
        sm[0] = mean;
        sm[1] = rsqrtf(var + 1e-5f);
    }
    __syncthreads();
    float mean = sm[0], inv = sm[1];
#pragma unroll
    for (int i = 0; i < 4; i++) {
        int c = threadIdx.x + i * 128;
        orow[c] = __float2half((v[i] - mean) * inv * w[c] + b[c]);
    }
}

// ---------------- fp16 mma.sync GEMM, KTILE=64 ------------------------------
// C[M,N] = A[M,K] @ Bt[N,K]^T + bias. A,Bt half.
// epi: 0=bias->Cf; 1=bias+relu->Ch; 2=bias+add1+add2->Cf; 3=bias+add1->Cf; 4=bias->Ch
__global__ void __launch_bounds__(256)
hgemm(const __half* __restrict__ A, const __half* __restrict__ Bt,
      const float* __restrict__ bias, float* __restrict__ Cf, __half* __restrict__ Ch,
      int N, int K, int epi,
      const float* __restrict__ add1, const float* __restrict__ add2) {
    extern __shared__ __half smh[];
    __half* Abuf[2] = { smh,         smh + 2 * TILEH };
    __half* Bbuf[2] = { smh + TILEH, smh + 3 * TILEH };
    int tid = threadIdx.x;
    int lane = tid & 31, wid = tid >> 5;
    int wm = (wid & 3) * 32;
    int wn = (wid >> 2) * 64;
    int g = lane >> 2, c = lane & 3;
    int rowBase = blockIdx.y * 128, colBase = blockIdx.x * 128;

    // staging: tile = 128 rows x 64 halfs (128B) = 8 chunks/row; 1024 chunks; 4/thread
    int srow[4], sseg[4];
#pragma unroll
    for (int u = 0; u < 4; u++) {
        int f = tid + 256 * u;
        srow[u] = f >> 3;
        sseg[u] = f & 7;
    }

    float acc[2][8][4];
#pragma unroll
    for (int i = 0; i < 2; i++)
#pragma unroll
        for (int j = 0; j < 8; j++)
#pragma unroll
            for (int q = 0; q < 4; q++) acc[i][j][q] = 0.f;

    int nk = K >> 6;
    const __half* Arow = A + (size_t)rowBase * K;
    const __half* Brow = Bt + (size_t)colBase * K;

#pragma unroll
    for (int u = 0; u < 4; u++) {
        cp16(smem_u32(Abuf[0] + srow[u] * LDWH + sseg[u] * 8),
             Arow + (size_t)srow[u] * K + sseg[u] * 8, true);
        cp16(smem_u32(Bbuf[0] + srow[u] * LDWH + sseg[u] * 8),
             Brow + (size_t)srow[u] * K + sseg[u] * 8, true);
    }
    CP_COMMIT();

    for (int kt = 0; kt < nk; kt++) {
        int buf = kt & 1;
        if (kt + 1 < nk) {
            int nb = buf ^ 1;
            const __half* Ag = Arow + (size_t)(kt + 1) * KT;
            const __half* Bg = Brow + (size_t)(kt + 1) * KT;
#pragma unroll
            for (int u = 0; u < 4; u++) {
                cp16(smem_u32(Abuf[nb] + srow[u] * LDWH + sseg[u] * 8),
                     Ag + (size_t)srow[u] * K + sseg[u] * 8, true);
                cp16(smem_u32(Bbuf[nb] + srow[u] * LDWH + sseg[u] * 8),
                     Bg + (size_t)srow[u] * K + sseg[u] * 8, true);
            }
            CP_COMMIT();
            CP_WAIT1();
        } else {
            CP_WAIT0();
        }
        __syncthreads();
        const uint32_t* As = (const uint32_t*)Abuf[buf];   // LDWW words per row
        const uint32_t* Bs = (const uint32_t*)Bbuf[buf];
#pragma unroll
        for (int ks = 0; ks < 4; ks++) {                   // four k16 steps
            int kw = ks * 8;
            uint32_t a[2][4];
#pragma unroll
            for (int mt = 0; mt < 2; mt++) {
                const uint32_t* ap = As + (wm + mt * 16 + g) * LDWW + kw;
                const uint32_t* ap8 = ap + 8 * LDWW;
                a[mt][0] = ap[c];
                a[mt][1] = ap8[c];
                a[mt][2] = ap[c + 4];
                a[mt][3] = ap8[c + 4];
            }
#pragma unroll
            for (int nt = 0; nt < 8; nt++) {
                const uint32_t* bp = Bs + (wn + nt * 8 + g) * LDWW + kw;
                uint32_t b0 = bp[c];
                uint32_t b1 = bp[c + 4];
                MMAH(acc[0][nt], a[0][0], a[0][1], a[0][2], a[0][3], b0, b1);
                MMAH(acc[1][nt], a[1][0], a[1][1], a[1][2], a[1][3], b0, b1);
            }
        }
        __syncthreads();
    }

    // epilogue
#pragma unroll
    for (int mt = 0; mt < 2; mt++) {
#pragma unroll
        for (int nt = 0; nt < 8; nt++) {
            int cb = colBase + wn + nt * 8 + 2 * c;
            float bs0 = bias[cb], bs1 = bias[cb + 1];
#pragma unroll
            for (int half = 0; half < 2; half++) {
                int r = rowBase + wm + mt * 16 + g + half * 8;
                float v0 = acc[mt][nt][half * 2 + 0] + bs0;
                float v1 = acc[mt][nt][half * 2 + 1] + bs1;
                if (epi == 1) {
                    *(__half2*)(Ch + (size_t)r * N + cb) =
                        __floats2half2_rn(fmaxf(v0, 0.f), fmaxf(v1, 0.f));
                    continue;
                } else if (epi == 4) {
                    *(__half2*)(Ch + (size_t)r * N + cb) = __floats2half2_rn(v0, v1);
                    continue;
                } else if (epi == 2) {
                    size_t id = (size_t)r * 512 + cb;
                    v0 += add1[id] + add2[id];
                    v1 += add1[id + 1] + add2[id + 1];
                } else if (epi == 3) {
                    size_t id = (size_t)r * 512 + cb;
                    v0 += add1[id];
                    v1 += add1[id + 1];
                }
                *(float2*)(Cf + (size_t)r * N + cb) = make_float2(v0, v1);
            }
        }
    }
}

// ---------------- FSMN conv via fp16 mma, KTILE=64 --------------------------
__global__ void __launch_bounds__(256)
hconv(const __half* __restrict__ vm, const __half* __restrict__ qkv,
      const float* __restrict__ masks, float* __restrict__ out) {
    extern __shared__ __half smh[];
    __half* Abuf[2] = { smh,         smh + 2 * TILEH };
    __half* Bbuf[2] = { smh + TILEH, smh + 3 * TILEH };
    int tid = threadIdx.x;
    int lane = tid & 31, wid = tid >> 5;
    int wm = (wid & 3) * 32;
    int wn = (wid >> 2) * 64;
    int g = lane >> 2, c = lane & 3;
    int rowBase = blockIdx.y * 128, colBase = blockIdx.x * 128;

    int srow[4], sseg[4], sb[4], st[4];
#pragma unroll
    for (int u = 0; u < 4; u++) {
        int f = tid + 256 * u;
        srow[u] = f >> 3;
        sseg[u] = f & 7;
        int grow = rowBase + srow[u];
        sb[u] = grow / T_;
        st[u] = grow - sb[u] * T_;
    }

    float acc[2][8][4];
#pragma unroll
    for (int i = 0; i < 2; i++)
#pragma unroll
        for (int j = 0; j < 8; j++)
#pragma unroll
            for (int q = 0; q < 4; q++) acc[i][j][q] = 0.f;

    const int NT = 11 * 8;   // 11 taps x 8 ktiles (D_/KT)
    // stage iter 0 (tap 0, kt 0)
#pragma unroll
    for (int u = 0; u < 4; u++) {
        int src = st[u] - 5;
        bool ok = (unsigned)src < (unsigned)T_;
        cp16(smem_u32(Abuf[0] + srow[u] * LDWH + sseg[u] * 8),
             vm + ((size_t)(sb[u] * T_ + (ok ? src : 0)) * D_ + sseg[u] * 8), ok);
        cp16(smem_u32(Bbuf[0] + srow[u] * LDWH + sseg[u] * 8),
             g_kwt + ((size_t)(colBase + srow[u]) * D_ + sseg[u] * 8), true);
    }
    CP_COMMIT();

    for (int ti = 0; ti < NT; ti++) {
        int buf = ti & 1;
        if (ti + 1 < NT) {
            int nb = buf ^ 1;
            int tap = (ti + 1) >> 3, kt = (ti + 1) & 7;
            const __half* Bg = g_kwt + (size_t)tap * D_ * D_ + (size_t)colBase * D_ + kt * KT;
#pragma unroll
            for (int u = 0; u < 4; u++) {
                int src = st[u] + tap - 5;
                bool ok = (unsigned)src < (unsigned)T_;
                cp16(smem_u32(Abuf[nb] + srow[u] * LDWH + sseg[u] * 8),
                     vm + ((size_t)(sb[u] * T_ + (ok ? src : 0)) * D_ + kt * KT + sseg[u] * 8), ok);
                cp16(smem_u32(Bbuf[nb] + srow[u] * LDWH + sseg[u] * 8),
                     Bg + (size_t)srow[u] * D_ + sseg[u] * 8, true);
            }
            CP_COMMIT();
            CP_WAIT1();
        } else {
            CP_WAIT0();
        }
        __syncthreads();
        const uint32_t* As = (const uint32_t*)Abuf[buf];
        const uint32_t* Bs = (const uint32_t*)Bbuf[buf];
#pragma unroll
        for (int ks = 0; ks < 4; ks++) {
            int kw = ks * 8;
            uint32_t a[2][4];
#pragma unroll
            for (int mt = 0; mt < 2; mt++) {
                const uint32_t* ap = As + (wm + mt * 16 + g) * LDWW + kw;
                const uint32_t* ap8 = ap + 8 * LDWW;
                a[mt][0] = ap[c];
                a[mt][1] = ap8[c];
                a[mt][2] = ap[c + 4];
                a[mt][3] = ap8[c + 4];
            }
#pragma unroll
            for (int nt = 0; nt < 8; nt++) {
                const uint32_t* bp = Bs + (wn + nt * 8 + g) * LDWW + kw;
                uint32_t b0 = bp[c];
                uint32_t b1 = bp[c + 4];
                MMAH(acc[0][nt], a[0][0], a[0][1], a[0][2], a[0][3], b0, b1);
                MMAH(acc[1][nt], a[1][0], a[1][1], a[1][2], a[1][3], b0, b1);
            }
        }
        __syncthreads();
    }

    // epilogue: out = (acc + v*m) * m
#pragma unroll
    for (int mt = 0; mt < 2; mt++) {
#pragma unroll
        for (int nt = 0; nt < 8; nt++) {
            int cb = colBase + wn + nt * 8 + 2 * c;
#pragma unroll
            for (int half = 0; half < 2; half++) {
                int r = rowBase + wm + mt * 16 + g + half * 8;
                float m = masks[r];
                float v0 = __half2float(qkv[(size_t)r * QKVW + 1024 + cb]);
                float v1 = __half2float(qkv[(size_t)r * QKVW + 1024 + cb + 1]);
                float o0 = (acc[mt][nt][half * 2 + 0] + v0 * m) * m;
                float o1 = (acc[mt][nt][half * 2 + 1] + v1 * m) * m;
                *(float2*)(out + (size_t)r * D_ + cb) = make_float2(o0, o1);
            }
        }
    }
}

// ---------------- attention (half inputs, fp32 math) ------------------------
__global__ void scores_kernel(const __half* __restrict__ qkv, const float* __restrict__ masks,
                              float* __restrict__ scores) {
    int bh = blockIdx.z;
    int b = bh >> 2, h = bh & 3;
    int qbase = blockIdx.y * 32;
    int kbase = blockIdx.x * 32;
    __shared__ float Qs[32][33];
    __shared__ float Ks[32][33];
    int tid = threadIdx.x;
    int tx = tid & 15, ty = tid >> 4;
    float acc[2][2] = {};
    const int qoff = h * DK_;
    const int koff = D_ + h * DK_;
    for (int kc = 0; kc < DK_; kc += 32) {
#pragma unroll
        for (int i = 0; i < 2; i++) {
            int e = tid + 256 * i;                 // half2 slot: 512 total
            int rr = e >> 4, cc2 = e & 15;
            int qr = qbase + rr;
            __half2 qv = (qr < T_) ? *(const __half2*)(qkv + (size_t)(b * T_ + qr) * QKVW + qoff + kc + cc2 * 2)
                                   : __half2half2(__float2half(0.f));
            float2 qf = __half22float2(qv);
            Qs[rr][cc2 * 2] = qf.x; Qs[rr][cc2 * 2 + 1] = qf.y;
            int kr = kbase + rr;
            __half2 kv = (kr < T_) ? *(const __half2*)(qkv + (size_t)(b * T_ + kr) * QKVW + koff + kc + cc2 * 2)
                                   : __half2half2(__float2half(0.f));
            float2 kf = __half22float2(kv);
            Ks[rr][cc2 * 2] = kf.x; Ks[rr][cc2 * 2 + 1] = kf.y;
        }
        __syncthreads();
#pragma unroll
        for (int kk = 0; kk < 32; kk++) {
            float q0 = Qs[ty * 2 + 0][kk], q1 = Qs[ty * 2 + 1][kk];
            float k0 = Ks[tx * 2 + 0][kk], k1 = Ks[tx * 2 + 1][kk];
            acc[0][0] += q0 * k0; acc[0][1] += q0 * k1;
            acc[1][0] += q1 * k0; acc[1][1] += q1 * k1;
        }
        __syncthreads();
    }
    const float scale = 0.08838834764831845f;
#pragma unroll
    for (int i = 0; i < 2; i++) {
        int r = qbase + ty * 2 + i;
        if (r >= T_) continue;
#pragma unroll
        for (int j = 0; j < 2; j++) {
            int c = kbase + tx * 2 + j;
            if (c >= T_) continue;
            float s = acc[i][j] * scale;
            if (masks[b * T_ + c] <= 0.f) s = -3.0e38f;
            scores[((size_t)bh * T_ + r) * T_ + c] = s;
        }
    }
}

__global__ void softmax_kernel(float* __restrict__ scores) {
    float* p = scores + (size_t)blockIdx.x * T_;
    int tid = threadIdx.x;
    float v = (tid < T_) ? p[tid] : -3.4e38f;
    __shared__ float red[8];
    float m = v;
#pragma unroll
    for (int o = 16; o; o >>= 1) m = fmaxf(m, __shfl_xor_sync(~0u, m, o));
    if ((tid & 31) == 0) red[tid >> 5] = m;
    __syncthreads();
    if (tid < 8) {
        float t = red[tid];
#pragma unroll
        for (int o = 4; o; o >>= 1) t = fmaxf(t, __shfl_xor_sync(0xff, t, o));
        red[tid] = t;
    }
    __syncthreads();
    float mx = red[0];
    float e = (tid < T_) ? expf(v - mx) : 0.f;
    __syncthreads();
    float s = e;
#pragma unroll
    for (int o = 16; o; o >>= 1) s += __shfl_xor_sync(~0u, s, o);
    if ((tid & 31) == 0) red[tid >> 5] = s;
    __syncthreads();
    if (tid < 8) {
        float t = red[tid];
#pragma unroll
        for (int o = 4; o; o >>= 1) t += __shfl_xor_sync(0xff, t, o);
        red[tid] = t;
    }
    __syncthreads();
    float inv = 1.f / red[0];
    if (tid < T_) p[tid] = e * inv;
}

__global__ void ctx_kernel(const float* __restrict__ scores, const __half* __restrict__ qkv,
                           __half* __restrict__ ctx) {
    int bh = blockIdx.y;
    int b = bh >> 2, h = bh & 3;
    int t0 = blockIdx.x * 16;
    int nt = T_ - t0; if (nt > 16) nt = 16;
    __shared__ float at[16][T_];
    int tid = threadIdx.x;
    for (int e = tid; e < 16 * T_; e += 128) {
        int tt = e / T_, k = e % T_;
        at[tt][k] = (tt < nt) ? scores[((size_t)bh * T_ + t0 + tt) * T_ + k] : 0.f;
    }
    __syncthreads();
    float acc[16] = {};
    const int voff = 1024 + h * DK_;
    for (int k = 0; k < T_; k++) {
        float vk = __half2float(qkv[(size_t)(b * T_ + k) * QKVW + voff + tid]);
#pragma unroll
        for (int tt = 0; tt < 16; tt++) acc[tt] += at[tt][k] * vk;
    }
    for (int tt = 0; tt < nt; tt++)
        ctx[(size_t)(b * T_ + t0 + tt) * D_ + h * DK_ + tid] = __float2half(acc[tt]);
}

// ---------------- launch ------------------------------------------------------
extern "C" void kernel_launch(void* const* d_in, const int* in_sizes, int n_in,
                              void* d_out, int out_size) {
    const float* x     = (const float*)d_in[0];
    const float* masks = (const float*)d_in[1];
    const float* ln0_w = (const float*)d_in[2];
    const float* ln0_b = (const float*)d_in[3];
    const float* ln1_w = (const float*)d_in[4];
    const float* ln1_b = (const float*)d_in[5];
    const float* qkv_w = (const float*)d_in[6];
    const float* qkv_b = (const float*)d_in[7];
    const float* out_w = (const float*)d_in[8];
    const float* out_b = (const float*)d_in[9];
    const float* fsmn_w= (const float*)d_in[10];
    const float* w1    = (const float*)d_in[11];
    const float* b1    = (const float*)d_in[12];
    const float* w2    = (const float*)d_in[13];
    const float* b2    = (const float*)d_in[14];
    float* out = (float*)d_out;

    __half *h, *qkv, *vm, *ctx, *mid, *qkv_wt, *out_wt, *w1t, *w2t;
    float *fsmn, *scores, *x1;
    cudaGetSymbolAddress((void**)&h,      g_h);
    cudaGetSymbolAddress((void**)&qkv,    g_qkv);
    cudaGetSymbolAddress((void**)&vm,     g_vm);
    cudaGetSymbolAddress((void**)&fsmn,   g_fsmn);
    cudaGetSymbolAddress((void**)&scores, g_scores);
    cudaGetSymbolAddress((void**)&ctx,    g_ctx);
    cudaGetSymbolAddress((void**)&x1,     g_x1);
    cudaGetSymbolAddress((void**)&mid,    g_mid);
    cudaGetSymbolAddress((void**)&qkv_wt, g_qkv_wt);
    cudaGetSymbolAddress((void**)&out_wt, g_out_wt);
    cudaGetSymbolAddress((void**)&w1t,    g_w1t);
    cudaGetSymbolAddress((void**)&w2t,    g_w2t);

    cudaFuncSetAttribute(hgemm, cudaFuncAttributeMaxDynamicSharedMemorySize, DSMEM_BYTES);
    cudaFuncSetAttribute(hconv, cudaFuncAttributeMaxDynamicSharedMemorySize, DSMEM_BYTES);

    // weight prep (half, [N,K])
    transpose_h<<<dim3(QKVW / 32, D_ / 32), dim3(32, 8)>>>(qkv_w, qkv_wt, D_, QKVW);
    transpose_h<<<dim3(D_ / 32, D_ / 32), dim3(32, 8)>>>(out_w, out_wt, D_, D_);
    transpose_h<<<dim3(2048 / 32, D_ / 32), dim3(32, 8)>>>(w1, w1t, D_, 2048);
    transpose_h<<<dim3(D_ / 32, 2048 / 32), dim3(32, 8)>>>(w2, w2t, 2048, D_);
    kw_transpose<<<(11 * D_ * D_ + 255) / 256, 256>>>(fsmn_w);

    // LN0 -> half h
    ln_kernel<<<R_, 128>>>(x, ln0_w, ln0_b, h);

    // QKV -> half qkv (epi 4)
    hgemm<<<dim3(QKVW / 128, R_ / 128), 256, DSMEM_BYTES>>>(h, qkv_wt, qkv_b, nullptr, qkv,
                                                            QKVW, D_, 4, nullptr, nullptr);
    // masked v -> half
    vm_kernel<<<R_ * D_ / 256, 256>>>(qkv, masks, vm);

    // FSMN conv
    hconv<<<dim3(D_ / 128, R_ / 128), 256, DSMEM_BYTES>>>(vm, qkv, masks, fsmn);

    // attention
    scores_kernel<<<dim3(7, 7, B_ * H_), 256>>>(qkv, masks, scores);
    softmax_kernel<<<B_ * H_ * T_, 256>>>(scores);
    ctx_kernel<<<dim3((T_ + 15) / 16, B_ * H_), 128>>>(scores, qkv, ctx);

    // out proj + fsmn + residual -> x1
    hgemm<<<dim3(D_ / 128, R_ / 128), 256, DSMEM_BYTES>>>(ctx, out_wt, out_b, x1, nullptr,
                                                          D_, D_, 2, fsmn, x);
    // LN1 -> half h
    ln_kernel<<<R_, 128>>>(x1, ln1_w, ln1_b, h);

    // FFN
    hgemm<<<dim3(2048 / 128, R_ / 128), 256, DSMEM_BYTES>>>(h, w1t, b1, nullptr, mid,
                                                            2048, D_, 1, nullptr, nullptr);
    hgemm<<<dim3(D_ / 128, R_ / 128), 256, DSMEM_BYTES>>>(mid, w2t, b2, out, nullptr,
                                                          D_, 2048, 3, x1, nullptr);
    (void)in_sizes; (void)n_in; (void)out_size;
}